// round 1
// baseline (speedup 1.0000x reference)
#include <cuda_runtime.h>
#include <math.h>

#define Bb 8
#define Nn 4096
#define Cc 512
#define Hh 8
#define DHd 64
#define Tt (Bb*Nn)   // 32768 tokens

// Scratch (allocation-free rule: device globals)
__device__ float g_xn[Tt*Cc];                 // LayerNorm output  [T, C]
__device__ float g_qkv[3*Bb*Hh*DHd*Nn];       // [i][b][h][d][n]
__device__ float g_y[Tt*Cc];                  // gelu(attn@v) in [T, C]

// ---------------------------------------------------------------------------
// K1: LayerNorm. one block (128 thr) per token, C=512 -> one float4 per thread
// ---------------------------------------------------------------------------
__global__ void ln_kernel(const float* __restrict__ x,
                          const float* __restrict__ gam,
                          const float* __restrict__ bet) {
    const int t = blockIdx.x;
    const int tid = threadIdx.x;           // 128
    const float4 xv = *(const float4*)(x + (size_t)t*Cc + tid*4);
    float s  = xv.x + xv.y + xv.z + xv.w;
    float ss = xv.x*xv.x + xv.y*xv.y + xv.z*xv.z + xv.w*xv.w;
    #pragma unroll
    for (int o = 16; o > 0; o >>= 1) {
        s  += __shfl_xor_sync(0xffffffffu, s,  o);
        ss += __shfl_xor_sync(0xffffffffu, ss, o);
    }
    __shared__ float shs[4], shss[4];
    const int w = tid >> 5, l = tid & 31;
    if (l == 0) { shs[w] = s; shss[w] = ss; }
    __syncthreads();
    const float tot  = shs[0]  + shs[1]  + shs[2]  + shs[3];
    const float tots = shss[0] + shss[1] + shss[2] + shss[3];
    const float mean = tot * (1.0f/512.0f);
    const float var  = tots * (1.0f/512.0f) - mean*mean;
    const float inv  = rsqrtf(var + 1e-5f);
    const float4 gv = *(const float4*)(gam + tid*4);
    const float4 bv = *(const float4*)(bet + tid*4);
    float4 o;
    o.x = (xv.x - mean)*inv*gv.x + bv.x;
    o.y = (xv.y - mean)*inv*gv.y + bv.y;
    o.z = (xv.z - mean)*inv*gv.z + bv.z;
    o.w = (xv.w - mean)*inv*gv.w + bv.w;
    *(float4*)(g_xn + (size_t)t*Cc + tid*4) = o;
}

// ---------------------------------------------------------------------------
// SGEMM: C[t,o] = sum_c A[t,c] * W[o,c].  128x128 tile, K-tile 16, 256 thr,
// 8x8 per thread as two 4-wide float4 fragments (vectorized LDS).
// EPI=0: A=g_xn, scatter into g_qkv [i][b][h][d][n] (float4 along n)
// EPI=1: A=g_y,  out[t*512+o] = acc + bias[o]       (float4 along o)
// ---------------------------------------------------------------------------
template<int EPI>
__global__ void __launch_bounds__(256) sgemm_kernel(const float* __restrict__ W,
                                                    const float* __restrict__ bias,
                                                    float* __restrict__ out) {
    __shared__ float As[16][128];
    __shared__ float Ws[16][128];
    const float* __restrict__ A = (EPI == 0) ? g_xn : g_y;
    const int tid = threadIdx.x;
    const int t0 = blockIdx.y * 128;
    const int o0 = blockIdx.x * 128;
    // lane mapping: fast (coalesced) dim follows the epilogue layout
    const int mL = (EPI == 0) ? (tid & 15) : (tid >> 4);
    const int nL = (EPI == 0) ? (tid >> 4) : (tid & 15);

    float acc[8][8];
    #pragma unroll
    for (int i = 0; i < 8; i++)
        #pragma unroll
        for (int j = 0; j < 8; j++) acc[i][j] = 0.0f;

    for (int k0 = 0; k0 < 512; k0 += 16) {
        #pragma unroll
        for (int j = 0; j < 2; j++) {
            const int idx = tid*2 + j;            // 0..511
            const int r  = idx >> 2;              // 0..127
            const int c  = (idx & 3) * 4;         // 0,4,8,12
            float4 av = *(const float4*)(A + (size_t)(t0 + r)*512 + k0 + c);
            As[c+0][r] = av.x; As[c+1][r] = av.y; As[c+2][r] = av.z; As[c+3][r] = av.w;
            float4 wv = *(const float4*)(W + (size_t)(o0 + r)*512 + k0 + c);
            Ws[c+0][r] = wv.x; Ws[c+1][r] = wv.y; Ws[c+2][r] = wv.z; Ws[c+3][r] = wv.w;
        }
        __syncthreads();
        #pragma unroll
        for (int kk = 0; kk < 16; kk++) {
            float4 a0 = *(const float4*)&As[kk][mL*4];
            float4 a1 = *(const float4*)&As[kk][64 + mL*4];
            float4 b0 = *(const float4*)&Ws[kk][nL*4];
            float4 b1 = *(const float4*)&Ws[kk][64 + nL*4];
            const float a[8] = {a0.x,a0.y,a0.z,a0.w, a1.x,a1.y,a1.z,a1.w};
            const float b[8] = {b0.x,b0.y,b0.z,b0.w, b1.x,b1.y,b1.z,b1.w};
            #pragma unroll
            for (int mi = 0; mi < 8; mi++)
                #pragma unroll
                for (int ni = 0; ni < 8; ni++)
                    acc[mi][ni] = fmaf(a[mi], b[ni], acc[mi][ni]);
        }
        __syncthreads();
    }

    if (EPI == 0) {
        // m fragment: t = t0 + mg*64 + mL*4 + q  (4 consecutive tokens -> 4 consecutive n)
        #pragma unroll
        for (int mg = 0; mg < 2; mg++) {
            const int tbase = t0 + mg*64 + mL*4;
            const int b = tbase >> 12;
            const int n = tbase & 4095;
            #pragma unroll
            for (int ng = 0; ng < 2; ng++)
                #pragma unroll
                for (int q = 0; q < 4; q++) {
                    const int o = o0 + ng*64 + nL*4 + q;
                    const int i = o >> 9, hh = (o >> 6) & 7, d = o & 63;
                    const int row = ((i*Bb + b)*Hh + hh)*DHd + d;
                    float4 v;
                    v.x = acc[mg*4+0][ng*4+q];
                    v.y = acc[mg*4+1][ng*4+q];
                    v.z = acc[mg*4+2][ng*4+q];
                    v.w = acc[mg*4+3][ng*4+q];
                    *(float4*)(g_qkv + ((size_t)row << 12) + n) = v;
                }
        }
    } else {
        #pragma unroll
        for (int mg = 0; mg < 2; mg++)
            #pragma unroll
            for (int q = 0; q < 4; q++) {
                const int t = t0 + mg*64 + mL*4 + q;
                #pragma unroll
                for (int ng = 0; ng < 2; ng++) {
                    const int o = o0 + ng*64 + nL*4;
                    const float4 bsv = *(const float4*)(bias + o);
                    float4 v;
                    v.x = acc[mg*4+q][ng*4+0] + bsv.x;
                    v.y = acc[mg*4+q][ng*4+1] + bsv.y;
                    v.z = acc[mg*4+q][ng*4+2] + bsv.z;
                    v.w = acc[mg*4+q][ng*4+3] + bsv.w;
                    *(float4*)(out + (size_t)t*512 + o) = v;
                }
            }
    }
}

// ---------------------------------------------------------------------------
// K3: L2-normalize q and k rows (length N=4096) in place; fold temperature
// into q. 8192 rows (i=0 q rows then i=1 k rows), one block (256 thr) per row.
// ---------------------------------------------------------------------------
__global__ void l2norm_kernel(const float* __restrict__ temperature) {
    const int row = blockIdx.x;                 // 0..8191
    float* p = g_qkv + (size_t)row * 4096;
    const int tid = threadIdx.x;                // 256
    float4 v[4];
    float ss = 0.0f;
    #pragma unroll
    for (int j = 0; j < 4; j++) {
        v[j] = *(const float4*)(p + j*1024 + tid*4);
        ss += v[j].x*v[j].x + v[j].y*v[j].y + v[j].z*v[j].z + v[j].w*v[j].w;
    }
    #pragma unroll
    for (int o = 16; o > 0; o >>= 1) ss += __shfl_xor_sync(0xffffffffu, ss, o);
    __shared__ float sh[8];
    const int w = tid >> 5, l = tid & 31;
    if (l == 0) sh[w] = ss;
    __syncthreads();
    float tot = 0.0f;
    #pragma unroll
    for (int j = 0; j < 8; j++) tot += sh[j];
    const float factor = (row < Bb*Hh*DHd) ? temperature[(row >> 6) & 7] : 1.0f;
    const float scale = factor / fmaxf(sqrtf(tot), 1e-12f);
    #pragma unroll
    for (int j = 0; j < 4; j++) {
        v[j].x *= scale; v[j].y *= scale; v[j].z *= scale; v[j].w *= scale;
        *(float4*)(p + j*1024 + tid*4) = v[j];
    }
}

// ---------------------------------------------------------------------------
// K4: per (b,h): S = q k^T (64x64 over n=4096), softmax (temperature already
// folded into q), out = attn @ v, exact GELU, write to g_y in [b,n,c] layout.
// 64 blocks x 256 threads. 16x16 thread grid, 4x4 per thread.
// ---------------------------------------------------------------------------
#define PAD 65
__global__ void __launch_bounds__(256) attn_kernel() {
    __shared__ float buf[2*64*PAD];            // phase A: qs|ks ; phase B: attn|vs
    float* qs = buf;
    float* ks = buf + 64*PAD;
    const int bh = blockIdx.x;                  // b*8+h
    const int b = bh >> 3, h = bh & 7;
    const float* __restrict__ q = g_qkv + (size_t)(0*64 + bh) * 64 * 4096;
    const float* __restrict__ k = g_qkv + (size_t)(1*64 + bh) * 64 * 4096;
    const float* __restrict__ v = g_qkv + (size_t)(2*64 + bh) * 64 * 4096;
    const int tid = threadIdx.x;
    const int tx = tid & 15, ty = tid >> 4;

    // ---- Phase A: S[d][e] with d = ty*4+i, e = tx*4+j ----
    float S[4][4];
    #pragma unroll
    for (int i = 0; i < 4; i++)
        #pragma unroll
        for (int j = 0; j < 4; j++) S[i][j] = 0.0f;

    for (int n0 = 0; n0 < 4096; n0 += 64) {
        #pragma unroll
        for (int j = 0; j < 4; j++) {
            const int idx = j*256 + tid;        // 0..1023
            const int r = idx >> 4;             // row (d/e) 0..63
            const int c = (idx & 15) * 4;       // col within chunk
            float4 qv = *(const float4*)(q + (size_t)r*4096 + n0 + c);
            qs[r*PAD + c+0] = qv.x; qs[r*PAD + c+1] = qv.y;
            qs[r*PAD + c+2] = qv.z; qs[r*PAD + c+3] = qv.w;
            float4 kv = *(const float4*)(k + (size_t)r*4096 + n0 + c);
            ks[r*PAD + c+0] = kv.x; ks[r*PAD + c+1] = kv.y;
            ks[r*PAD + c+2] = kv.z; ks[r*PAD + c+3] = kv.w;
        }
        __syncthreads();
        #pragma unroll 8
        for (int n = 0; n < 64; n++) {
            float qr[4], kr[4];
            #pragma unroll
            for (int i = 0; i < 4; i++) qr[i] = qs[(ty*4+i)*PAD + n];
            #pragma unroll
            for (int j = 0; j < 4; j++) kr[j] = ks[(tx*4+j)*PAD + n];
            #pragma unroll
            for (int i = 0; i < 4; i++)
                #pragma unroll
                for (int j = 0; j < 4; j++)
                    S[i][j] = fmaf(qr[i], kr[j], S[i][j]);
        }
        __syncthreads();
    }

    // ---- Softmax over e (row d split across the 16 tx lanes of a half-warp)
    float* attn = buf;                          // alias qs (phase A done)
    float* vs   = buf + 64*PAD;                 // alias ks
    #pragma unroll
    for (int i = 0; i < 4; i++) {
        float mx = fmaxf(fmaxf(S[i][0], S[i][1]), fmaxf(S[i][2], S[i][3]));
        #pragma unroll
        for (int o = 8; o > 0; o >>= 1) mx = fmaxf(mx, __shfl_xor_sync(0xffffffffu, mx, o));
        float e[4], sm = 0.0f;
        #pragma unroll
        for (int j = 0; j < 4; j++) { e[j] = __expf(S[i][j] - mx); sm += e[j]; }
        #pragma unroll
        for (int o = 8; o > 0; o >>= 1) sm += __shfl_xor_sync(0xffffffffu, sm, o);
        const float inv = 1.0f / sm;
        #pragma unroll
        for (int j = 0; j < 4; j++) attn[(ty*4+i)*PAD + tx*4+j] = e[j] * inv;
    }
    __syncthreads();

    // ---- Phase B: out[d][n] = sum_e attn[d][e] * v[e][n]; gelu; write [b,n,c]
    // thread: d = tx*4+j (4 consecutive -> float4 write), n = n0 + ty*4 + i
    for (int n0 = 0; n0 < 4096; n0 += 64) {
        #pragma unroll
        for (int j = 0; j < 4; j++) {
            const int idx = j*256 + tid;
            const int r = idx >> 4;
            const int c = (idx & 15) * 4;
            float4 vv = *(const float4*)(v + (size_t)r*4096 + n0 + c);
            vs[r*PAD + c+0] = vv.x; vs[r*PAD + c+1] = vv.y;
            vs[r*PAD + c+2] = vv.z; vs[r*PAD + c+3] = vv.w;
        }
        __syncthreads();
        float acc[4][4];
        #pragma unroll
        for (int i = 0; i < 4; i++)
            #pragma unroll
            for (int j = 0; j < 4; j++) acc[i][j] = 0.0f;
        #pragma unroll 8
        for (int e = 0; e < 64; e++) {
            float ar[4], vr[4];
            #pragma unroll
            for (int j = 0; j < 4; j++) ar[j] = attn[(tx*4+j)*PAD + e];
            #pragma unroll
            for (int i = 0; i < 4; i++) vr[i] = vs[e*PAD + ty*4 + i];
            #pragma unroll
            for (int i = 0; i < 4; i++)
                #pragma unroll
                for (int j = 0; j < 4; j++)
                    acc[i][j] = fmaf(ar[j], vr[i], acc[i][j]);
        }
        #pragma unroll
        for (int i = 0; i < 4; i++) {
            const int n = n0 + ty*4 + i;
            const size_t t = (size_t)b*4096 + n;
            float4 o;
            float xg;
            xg = acc[i][0]; o.x = 0.5f*xg*(1.0f + erff(xg*0.70710678118654752f));
            xg = acc[i][1]; o.y = 0.5f*xg*(1.0f + erff(xg*0.70710678118654752f));
            xg = acc[i][2]; o.z = 0.5f*xg*(1.0f + erff(xg*0.70710678118654752f));
            xg = acc[i][3]; o.w = 0.5f*xg*(1.0f + erff(xg*0.70710678118654752f));
            *(float4*)(g_y + t*512 + h*64 + tx*4) = o;
        }
        __syncthreads();
    }
}

// ---------------------------------------------------------------------------
extern "C" void kernel_launch(void* const* d_in, const int* in_sizes, int n_in,
                              void* d_out, int out_size) {
    const float* x           = (const float*)d_in[0];
    const float* ln_g        = (const float*)d_in[1];
    const float* ln_b        = (const float*)d_in[2];
    const float* qkv_w       = (const float*)d_in[3];
    const float* temperature = (const float*)d_in[4];
    const float* proj_w      = (const float*)d_in[5];
    const float* proj_b      = (const float*)d_in[6];
    float* out = (float*)d_out;

    ln_kernel<<<Tt, 128>>>(x, ln_g, ln_b);
    sgemm_kernel<0><<<dim3(1536/128, Tt/128), 256>>>(qkv_w, nullptr, nullptr);
    l2norm_kernel<<<2*Bb*Hh*DHd, 256>>>(temperature);
    attn_kernel<<<Bb*Hh, 256>>>();
    sgemm_kernel<1><<<dim3(512/128, Tt/128), 256>>>(proj_w, proj_b, out);
}

// round 2
// speedup vs baseline: 1.1560x; 1.1560x over previous
#include <cuda_runtime.h>
#include <math.h>

#define Bb 8
#define Nn 4096
#define Cc 512
#define Hh 8
#define DHd 64
#define Tt (Bb*Nn)   // 32768 tokens

// Scratch (allocation-free rule: device globals)
__device__ float g_xn[Tt*Cc];                 // LayerNorm output  [T, C]
__device__ float g_qkv[3*Bb*Hh*DHd*Nn];       // [i][b][h][d][n]
__device__ float g_y[Tt*Cc];                  // gelu(attn@v) in [T, C]
__device__ float g_Sp[64*8*64*64];            // partial S per (bh, split)
__device__ float g_attn[64*64*64];            // softmaxed attn [bh][d][e]

// ---------------------------------------------------------------------------
// K1: LayerNorm. one block (128 thr) per token, C=512 -> one float4 per thread
// ---------------------------------------------------------------------------
__global__ void ln_kernel(const float* __restrict__ x,
                          const float* __restrict__ gam,
                          const float* __restrict__ bet) {
    const int t = blockIdx.x;
    const int tid = threadIdx.x;           // 128
    const float4 xv = *(const float4*)(x + (size_t)t*Cc + tid*4);
    float s  = xv.x + xv.y + xv.z + xv.w;
    float ss = xv.x*xv.x + xv.y*xv.y + xv.z*xv.z + xv.w*xv.w;
    #pragma unroll
    for (int o = 16; o > 0; o >>= 1) {
        s  += __shfl_xor_sync(0xffffffffu, s,  o);
        ss += __shfl_xor_sync(0xffffffffu, ss, o);
    }
    __shared__ float shs[4], shss[4];
    const int w = tid >> 5, l = tid & 31;
    if (l == 0) { shs[w] = s; shss[w] = ss; }
    __syncthreads();
    const float tot  = shs[0]  + shs[1]  + shs[2]  + shs[3];
    const float tots = shss[0] + shss[1] + shss[2] + shss[3];
    const float mean = tot * (1.0f/512.0f);
    const float var  = tots * (1.0f/512.0f) - mean*mean;
    const float inv  = rsqrtf(var + 1e-5f);
    const float4 gv = *(const float4*)(gam + tid*4);
    const float4 bv = *(const float4*)(bet + tid*4);
    float4 o;
    o.x = (xv.x - mean)*inv*gv.x + bv.x;
    o.y = (xv.y - mean)*inv*gv.y + bv.y;
    o.z = (xv.z - mean)*inv*gv.z + bv.z;
    o.w = (xv.w - mean)*inv*gv.w + bv.w;
    *(float4*)(g_xn + (size_t)t*Cc + tid*4) = o;
}

// ---------------------------------------------------------------------------
// SGEMM: C[t,o] = sum_c A[t,c] * W[o,c].  128x128 tile, K-tile 16, 256 thr,
// double-buffered smem with register prefetch (one sync per K-tile).
// EPI=0: A=g_xn, scatter into g_qkv [i][b][h][d][n] (float4 along n)
// EPI=1: A=g_y,  out[t*512+o] = acc + bias[o]       (float4 along o)
// ---------------------------------------------------------------------------
template<int EPI>
__global__ void __launch_bounds__(256) sgemm_kernel(const float* __restrict__ W,
                                                    const float* __restrict__ bias,
                                                    float* __restrict__ out) {
    __shared__ float As[2][16][128];
    __shared__ float Ws[2][16][128];
    const float* __restrict__ A = (EPI == 0) ? g_xn : g_y;
    const int tid = threadIdx.x;
    const int t0 = blockIdx.y * 128;
    const int o0 = blockIdx.x * 128;
    const int mL = (EPI == 0) ? (tid & 15) : (tid >> 4);
    const int nL = (EPI == 0) ? (tid >> 4) : (tid & 15);

    // global-load lane mapping (fixed per thread)
    int rr[2], cc[2];
    #pragma unroll
    for (int j = 0; j < 2; j++) {
        const int idx = tid*2 + j;
        rr[j] = idx >> 2;
        cc[j] = (idx & 3) * 4;
    }

    float acc[8][8];
    #pragma unroll
    for (int i = 0; i < 8; i++)
        #pragma unroll
        for (int j = 0; j < 8; j++) acc[i][j] = 0.0f;

    float4 pa[2], pw[2];
    #pragma unroll
    for (int j = 0; j < 2; j++) {
        pa[j] = *(const float4*)(A + (size_t)(t0 + rr[j])*512 + cc[j]);
        pw[j] = *(const float4*)(W + (size_t)(o0 + rr[j])*512 + cc[j]);
    }
    #pragma unroll
    for (int j = 0; j < 2; j++) {
        As[0][cc[j]+0][rr[j]] = pa[j].x; As[0][cc[j]+1][rr[j]] = pa[j].y;
        As[0][cc[j]+2][rr[j]] = pa[j].z; As[0][cc[j]+3][rr[j]] = pa[j].w;
        Ws[0][cc[j]+0][rr[j]] = pw[j].x; Ws[0][cc[j]+1][rr[j]] = pw[j].y;
        Ws[0][cc[j]+2][rr[j]] = pw[j].z; Ws[0][cc[j]+3][rr[j]] = pw[j].w;
    }
    __syncthreads();

    int buf = 0;
    for (int k0 = 0; k0 < 512; k0 += 16) {
        const int kn = k0 + 16;
        if (kn < 512) {
            #pragma unroll
            for (int j = 0; j < 2; j++) {
                pa[j] = *(const float4*)(A + (size_t)(t0 + rr[j])*512 + kn + cc[j]);
                pw[j] = *(const float4*)(W + (size_t)(o0 + rr[j])*512 + kn + cc[j]);
            }
        }
        #pragma unroll
        for (int kk = 0; kk < 16; kk++) {
            float4 a0 = *(const float4*)&As[buf][kk][mL*4];
            float4 a1 = *(const float4*)&As[buf][kk][64 + mL*4];
            float4 b0 = *(const float4*)&Ws[buf][kk][nL*4];
            float4 b1 = *(const float4*)&Ws[buf][kk][64 + nL*4];
            const float a[8] = {a0.x,a0.y,a0.z,a0.w, a1.x,a1.y,a1.z,a1.w};
            const float b[8] = {b0.x,b0.y,b0.z,b0.w, b1.x,b1.y,b1.z,b1.w};
            #pragma unroll
            for (int mi = 0; mi < 8; mi++)
                #pragma unroll
                for (int ni = 0; ni < 8; ni++)
                    acc[mi][ni] = fmaf(a[mi], b[ni], acc[mi][ni]);
        }
        if (kn < 512) {
            const int nb = buf ^ 1;
            #pragma unroll
            for (int j = 0; j < 2; j++) {
                As[nb][cc[j]+0][rr[j]] = pa[j].x; As[nb][cc[j]+1][rr[j]] = pa[j].y;
                As[nb][cc[j]+2][rr[j]] = pa[j].z; As[nb][cc[j]+3][rr[j]] = pa[j].w;
                Ws[nb][cc[j]+0][rr[j]] = pw[j].x; Ws[nb][cc[j]+1][rr[j]] = pw[j].y;
                Ws[nb][cc[j]+2][rr[j]] = pw[j].z; Ws[nb][cc[j]+3][rr[j]] = pw[j].w;
            }
        }
        __syncthreads();
        buf ^= 1;
    }

    if (EPI == 0) {
        #pragma unroll
        for (int mg = 0; mg < 2; mg++) {
            const int tbase = t0 + mg*64 + mL*4;
            const int b = tbase >> 12;
            const int n = tbase & 4095;
            #pragma unroll
            for (int ng = 0; ng < 2; ng++)
                #pragma unroll
                for (int q = 0; q < 4; q++) {
                    const int o = o0 + ng*64 + nL*4 + q;
                    const int i = o >> 9, hh = (o >> 6) & 7, d = o & 63;
                    const int row = ((i*Bb + b)*Hh + hh)*DHd + d;
                    float4 v;
                    v.x = acc[mg*4+0][ng*4+q];
                    v.y = acc[mg*4+1][ng*4+q];
                    v.z = acc[mg*4+2][ng*4+q];
                    v.w = acc[mg*4+3][ng*4+q];
                    *(float4*)(g_qkv + ((size_t)row << 12) + n) = v;
                }
        }
    } else {
        #pragma unroll
        for (int mg = 0; mg < 2; mg++)
            #pragma unroll
            for (int q = 0; q < 4; q++) {
                const int t = t0 + mg*64 + mL*4 + q;
                #pragma unroll
                for (int ng = 0; ng < 2; ng++) {
                    const int o = o0 + ng*64 + nL*4;
                    const float4 bsv = *(const float4*)(bias + o);
                    float4 v;
                    v.x = acc[mg*4+q][ng*4+0] + bsv.x;
                    v.y = acc[mg*4+q][ng*4+1] + bsv.y;
                    v.z = acc[mg*4+q][ng*4+2] + bsv.z;
                    v.w = acc[mg*4+q][ng*4+3] + bsv.w;
                    *(float4*)(out + (size_t)t*512 + o) = v;
                }
            }
    }
}

// ---------------------------------------------------------------------------
// K3: L2-normalize q and k rows (length N=4096) in place; fold temperature
// into q. 8192 rows, one block (256 thr) per row.
// ---------------------------------------------------------------------------
__global__ void l2norm_kernel(const float* __restrict__ temperature) {
    const int row = blockIdx.x;                 // 0..8191
    float* p = g_qkv + (size_t)row * 4096;
    const int tid = threadIdx.x;                // 256
    float4 v[4];
    float ss = 0.0f;
    #pragma unroll
    for (int j = 0; j < 4; j++) {
        v[j] = *(const float4*)(p + j*1024 + tid*4);
        ss += v[j].x*v[j].x + v[j].y*v[j].y + v[j].z*v[j].z + v[j].w*v[j].w;
    }
    #pragma unroll
    for (int o = 16; o > 0; o >>= 1) ss += __shfl_xor_sync(0xffffffffu, ss, o);
    __shared__ float sh[8];
    const int w = tid >> 5, l = tid & 31;
    if (l == 0) sh[w] = ss;
    __syncthreads();
    float tot = 0.0f;
    #pragma unroll
    for (int j = 0; j < 8; j++) tot += sh[j];
    const float factor = (row < Bb*Hh*DHd) ? temperature[(row >> 6) & 7] : 1.0f;
    const float scale = factor / fmaxf(sqrtf(tot), 1e-12f);
    #pragma unroll
    for (int j = 0; j < 4; j++) {
        v[j].x *= scale; v[j].y *= scale; v[j].z *= scale; v[j].w *= scale;
        *(float4*)(p + j*1024 + tid*4) = v[j];
    }
}

// ---------------------------------------------------------------------------
// K4a: partial S = q k^T over a 512-token slice of n. grid (64 bh, 8 splits).
// ---------------------------------------------------------------------------
#define PAD 65
__global__ void __launch_bounds__(256) attn_qk_kernel() {
    __shared__ float qs[64*PAD];
    __shared__ float ks[64*PAD];
    const int bh = blockIdx.x;
    const int split = blockIdx.y;
    const float* __restrict__ q = g_qkv + (size_t)(0*64 + bh) * 64 * 4096;
    const float* __restrict__ k = g_qkv + (size_t)(1*64 + bh) * 64 * 4096;
    const int tid = threadIdx.x;
    const int tx = tid & 15, ty = tid >> 4;

    float S[4][4];
    #pragma unroll
    for (int i = 0; i < 4; i++)
        #pragma unroll
        for (int j = 0; j < 4; j++) S[i][j] = 0.0f;

    const int nbeg = split * 512;
    for (int n0 = nbeg; n0 < nbeg + 512; n0 += 64) {
        #pragma unroll
        for (int j = 0; j < 4; j++) {
            const int idx = j*256 + tid;
            const int r = idx >> 4;
            const int c = (idx & 15) * 4;
            float4 qv = *(const float4*)(q + (size_t)r*4096 + n0 + c);
            qs[r*PAD + c+0] = qv.x; qs[r*PAD + c+1] = qv.y;
            qs[r*PAD + c+2] = qv.z; qs[r*PAD + c+3] = qv.w;
            float4 kv = *(const float4*)(k + (size_t)r*4096 + n0 + c);
            ks[r*PAD + c+0] = kv.x; ks[r*PAD + c+1] = kv.y;
            ks[r*PAD + c+2] = kv.z; ks[r*PAD + c+3] = kv.w;
        }
        __syncthreads();
        #pragma unroll 8
        for (int n = 0; n < 64; n++) {
            float qr[4], kr[4];
            #pragma unroll
            for (int i = 0; i < 4; i++) qr[i] = qs[(ty*4+i)*PAD + n];
            #pragma unroll
            for (int j = 0; j < 4; j++) kr[j] = ks[(tx*4+j)*PAD + n];
            #pragma unroll
            for (int i = 0; i < 4; i++)
                #pragma unroll
                for (int j = 0; j < 4; j++)
                    S[i][j] = fmaf(qr[i], kr[j], S[i][j]);
        }
        __syncthreads();
    }
    float* dst = g_Sp + ((size_t)(bh*8 + split)) * 4096;
    #pragma unroll
    for (int i = 0; i < 4; i++) {
        float4 v;
        v.x = S[i][0]; v.y = S[i][1]; v.z = S[i][2]; v.w = S[i][3];
        *(float4*)(dst + (ty*4+i)*64 + tx*4) = v;
    }
}

// ---------------------------------------------------------------------------
// K4b: reduce 8 partials + softmax over e. grid 64, block 256.
// ---------------------------------------------------------------------------
__global__ void __launch_bounds__(256) softmax_kernel() {
    __shared__ float S[64*PAD];
    const int bh = blockIdx.x;
    const int tid = threadIdx.x;
    for (int idx = tid; idx < 4096; idx += 256) {
        float s = 0.0f;
        #pragma unroll
        for (int sp = 0; sp < 8; sp++)
            s += g_Sp[((size_t)(bh*8 + sp))*4096 + idx];
        S[(idx >> 6)*PAD + (idx & 63)] = s;
    }
    __syncthreads();
    if (tid < 64) {
        const int d = tid;
        float mx = -1e30f;
        #pragma unroll 8
        for (int e = 0; e < 64; e++) mx = fmaxf(mx, S[d*PAD + e]);
        float sm = 0.0f;
        #pragma unroll 8
        for (int e = 0; e < 64; e++) {
            const float ex = __expf(S[d*PAD + e] - mx);
            S[d*PAD + e] = ex;
            sm += ex;
        }
        const float inv = 1.0f / sm;
        #pragma unroll 8
        for (int e = 0; e < 64; e++)
            g_attn[(size_t)bh*4096 + d*64 + e] = S[d*PAD + e] * inv;
    }
}

// ---------------------------------------------------------------------------
// K4c: out[d][n] = sum_e attn[d][e] v[e][n]; gelu; write g_y [b,n,c].
// grid (64 bh, 64 n-chunks), 256 thr.
// ---------------------------------------------------------------------------
__global__ void __launch_bounds__(256) attn_v_kernel() {
    __shared__ float attn[64*PAD];
    __shared__ float vs[64*PAD];
    const int bh = blockIdx.x;
    const int b = bh >> 3, h = bh & 7;
    const int n0 = blockIdx.y * 64;
    const float* __restrict__ v = g_qkv + (size_t)(2*64 + bh) * 64 * 4096;
    const int tid = threadIdx.x;
    const int tx = tid & 15, ty = tid >> 4;

    for (int idx = tid; idx < 4096; idx += 256)
        attn[(idx >> 6)*PAD + (idx & 63)] = g_attn[(size_t)bh*4096 + idx];
    #pragma unroll
    for (int j = 0; j < 4; j++) {
        const int idx = j*256 + tid;
        const int r = idx >> 4;
        const int c = (idx & 15) * 4;
        float4 vv = *(const float4*)(v + (size_t)r*4096 + n0 + c);
        vs[r*PAD + c+0] = vv.x; vs[r*PAD + c+1] = vv.y;
        vs[r*PAD + c+2] = vv.z; vs[r*PAD + c+3] = vv.w;
    }
    __syncthreads();

    float acc[4][4];
    #pragma unroll
    for (int i = 0; i < 4; i++)
        #pragma unroll
        for (int j = 0; j < 4; j++) acc[i][j] = 0.0f;
    #pragma unroll 8
    for (int e = 0; e < 64; e++) {
        float ar[4], vr[4];
        #pragma unroll
        for (int j = 0; j < 4; j++) ar[j] = attn[(tx*4+j)*PAD + e];
        #pragma unroll
        for (int i = 0; i < 4; i++) vr[i] = vs[e*PAD + ty*4 + i];
        #pragma unroll
        for (int i = 0; i < 4; i++)
            #pragma unroll
            for (int j = 0; j < 4; j++)
                acc[i][j] = fmaf(ar[j], vr[i], acc[i][j]);
    }
    #pragma unroll
    for (int i = 0; i < 4; i++) {
        const int n = n0 + ty*4 + i;
        const size_t t = (size_t)b*4096 + n;
        float4 o;
        float xg;
        xg = acc[i][0]; o.x = 0.5f*xg*(1.0f + erff(xg*0.70710678118654752f));
        xg = acc[i][1]; o.y = 0.5f*xg*(1.0f + erff(xg*0.70710678118654752f));
        xg = acc[i][2]; o.z = 0.5f*xg*(1.0f + erff(xg*0.70710678118654752f));
        xg = acc[i][3]; o.w = 0.5f*xg*(1.0f + erff(xg*0.70710678118654752f));
        *(float4*)(g_y + t*512 + h*64 + tx*4) = o;
    }
}

// ---------------------------------------------------------------------------
extern "C" void kernel_launch(void* const* d_in, const int* in_sizes, int n_in,
                              void* d_out, int out_size) {
    const float* x           = (const float*)d_in[0];
    const float* ln_g        = (const float*)d_in[1];
    const float* ln_b        = (const float*)d_in[2];
    const float* qkv_w       = (const float*)d_in[3];
    const float* temperature = (const float*)d_in[4];
    const float* proj_w      = (const float*)d_in[5];
    const float* proj_b      = (const float*)d_in[6];
    float* out = (float*)d_out;

    ln_kernel<<<Tt, 128>>>(x, ln_g, ln_b);
    sgemm_kernel<0><<<dim3(1536/128, Tt/128), 256>>>(qkv_w, nullptr, nullptr);
    l2norm_kernel<<<2*Bb*Hh*DHd, 256>>>(temperature);
    attn_qk_kernel<<<dim3(64, 8), 256>>>();
    softmax_kernel<<<64, 256>>>();
    attn_v_kernel<<<dim3(64, 64), 256>>>();
    sgemm_kernel<1><<<dim3(512/128, Tt/128), 256>>>(proj_w, proj_b, out);
}

// round 4
// speedup vs baseline: 2.7577x; 2.3856x over previous
#include <cuda_runtime.h>
#include <math.h>
#include <stdint.h>

#define Bb 8
#define Nn 4096
#define Cc 512
#define Hh 8
#define DHd 64
#define Tt (Bb*Nn)   // 32768 tokens

// Scratch (allocation-free rule: device globals)
__device__ float g_xn[Tt*Cc];                 // LayerNorm output [T,C], tf32-rounded
__device__ float g_qkv[3*Bb*Hh*DHd*Nn];       // [i][b][h][d][n] fp32
__device__ float g_y[Tt*Cc];                  // gelu(attn@v) [T,C], tf32-rounded
__device__ float g_Sp[64*8*64*64];            // partial S per (bh, split)
__device__ float g_attn[64*64*64];            // softmaxed attn [bh][d][e]
__device__ float g_wq[1536*512];              // tf32-rounded qkv_w
__device__ float g_wp[512*512];               // tf32-rounded proj_w

__device__ __forceinline__ uint32_t smem_u32(const void* p) {
    uint32_t a;
    asm("{ .reg .u64 t; cvta.to.shared.u64 t, %1; cvt.u32.u64 %0, t; }"
        : "=r"(a) : "l"(p));
    return a;
}
__device__ __forceinline__ float tf32r(float f) {
    uint32_t u;
    asm("cvt.rna.tf32.f32 %0, %1;" : "=r"(u) : "f"(f));
    return __uint_as_float(u);
}
__device__ __forceinline__ void cp16(uint32_t daddr, const float* src) {
    asm volatile("{ .reg .u64 p; cvta.to.global.u64 p, %1;"
                 "  cp.async.cg.shared.global [%0], [p], 16; }"
                 :: "r"(daddr), "l"(src) : "memory");
}

// ===========================================================================
// K0: round weights to tf32 representable values (rna)
// ===========================================================================
__global__ void round_w_kernel(const float* __restrict__ qkv_w,
                               const float* __restrict__ proj_w) {
    const int n1 = 1536*512/4, n2 = 512*512/4;
    for (int i = blockIdx.x*blockDim.x + threadIdx.x; i < n1 + n2;
         i += gridDim.x*blockDim.x) {
        const float4 v = (i < n1) ? ((const float4*)qkv_w)[i]
                                  : ((const float4*)proj_w)[i - n1];
        float4 o;
        o.x = tf32r(v.x); o.y = tf32r(v.y); o.z = tf32r(v.z); o.w = tf32r(v.w);
        if (i < n1) ((float4*)g_wq)[i] = o;
        else        ((float4*)g_wp)[i - n1] = o;
    }
}

// ===========================================================================
// K1: LayerNorm (outputs tf32-rounded)
// ===========================================================================
__global__ void ln_kernel(const float* __restrict__ x,
                          const float* __restrict__ gam,
                          const float* __restrict__ bet) {
    const int t = blockIdx.x;
    const int tid = threadIdx.x;           // 128
    const float4 xv = *(const float4*)(x + (size_t)t*Cc + tid*4);
    float s  = xv.x + xv.y + xv.z + xv.w;
    float ss = xv.x*xv.x + xv.y*xv.y + xv.z*xv.z + xv.w*xv.w;
    #pragma unroll
    for (int o = 16; o > 0; o >>= 1) {
        s  += __shfl_xor_sync(0xffffffffu, s,  o);
        ss += __shfl_xor_sync(0xffffffffu, ss, o);
    }
    __shared__ float shs[4], shss[4];
    const int w = tid >> 5, l = tid & 31;
    if (l == 0) { shs[w] = s; shss[w] = ss; }
    __syncthreads();
    const float tot  = shs[0]  + shs[1]  + shs[2]  + shs[3];
    const float tots = shss[0] + shss[1] + shss[2] + shss[3];
    const float mean = tot * (1.0f/512.0f);
    const float var  = tots * (1.0f/512.0f) - mean*mean;
    const float inv  = rsqrtf(var + 1e-5f);
    const float4 gv = *(const float4*)(gam + tid*4);
    const float4 bv = *(const float4*)(bet + tid*4);
    float4 o;
    o.x = tf32r((xv.x - mean)*inv*gv.x + bv.x);
    o.y = tf32r((xv.y - mean)*inv*gv.y + bv.y);
    o.z = tf32r((xv.z - mean)*inv*gv.z + bv.z);
    o.w = tf32r((xv.w - mean)*inv*gv.w + bv.w);
    *(float4*)(g_xn + (size_t)t*Cc + tid*4) = o;
}

// ===========================================================================
// tf32 mma.sync GEMM: C[t,o] = sum_c A[t,c]*W[o,c].
// Block 128(m) x 256(n), 256 thr (8 warps, 2x4), warp tile 64x64.
// Smem [m][k] ld=36 words, cp.async double buffer, ldmatrix frag loads.
// EPI=0: A=g_xn, W=g_wq -> scatter g_qkv.  EPI=1: A=g_y, W=g_wp -> out+bias.
// ===========================================================================
#define LDK 36
#define A_BYTES (128*LDK*4)      // 18432
#define W_BYTES (256*LDK*4)      // 36864
#define BUF_BYTES (A_BYTES + W_BYTES)  // 55296
#define GEMM_SMEM (2*BUF_BYTES)        // 110592

template<int EPI>
__global__ void __launch_bounds__(256, 1) mmagemm(const float* __restrict__ bias,
                                                  float* __restrict__ out) {
    extern __shared__ float smem[];
    const uint32_t sb = smem_u32(smem);
    const float* __restrict__ A = (EPI == 0) ? g_xn : g_y;
    const float* __restrict__ W = (EPI == 0) ? g_wq : g_wp;
    const int tid = threadIdx.x;
    const int wid = tid >> 5, lane = tid & 31;
    const int t0 = blockIdx.y * 128;
    const int o0 = blockIdx.x * 256;
    const int wm = wid >> 2, wn = wid & 3;
    const int g = lane >> 2, tg = lane & 3;

    // staging mapping
    int ra[4], ca[4], rw[8], cw[8];
    #pragma unroll
    for (int j = 0; j < 4; j++) { const int idx = j*256 + tid; ra[j] = idx >> 3; ca[j] = (idx & 7)*4; }
    #pragma unroll
    for (int j = 0; j < 8; j++) { const int idx = j*256 + tid; rw[j] = idx >> 3; cw[j] = (idx & 7)*4; }

    // ldmatrix lane base addresses
    const int l15 = lane & 15;
    const uint32_t baseA = sb + (uint32_t)(((wm*64 + l15)*LDK + ((lane & 16) ? 4 : 0)) * 4);
    const int l7 = lane & 7;
    const uint32_t baseB = sb + A_BYTES + (uint32_t)(((wn*64 + l7)*LDK + ((lane & 8) ? 4 : 0)) * 4);

    float acc[4][8][4];
    #pragma unroll
    for (int mt = 0; mt < 4; mt++)
        #pragma unroll
        for (int nt = 0; nt < 8; nt++)
            #pragma unroll
            for (int r = 0; r < 4; r++) acc[mt][nt][r] = 0.0f;

    // prologue: stage tile 0 into buffer 0
    {
        const uint32_t sA = sb, sW = sb + A_BYTES;
        #pragma unroll
        for (int j = 0; j < 4; j++)
            cp16(sA + (ra[j]*LDK + ca[j])*4, A + (size_t)(t0 + ra[j])*512 + ca[j]);
        #pragma unroll
        for (int j = 0; j < 8; j++)
            cp16(sW + (rw[j]*LDK + cw[j])*4, W + (size_t)(o0 + rw[j])*512 + cw[j]);
        asm volatile("cp.async.commit_group;" ::: "memory");
    }

    for (int c = 0; c < 16; c++) {
        const int buf = c & 1;
        asm volatile("cp.async.wait_group 0;" ::: "memory");
        __syncthreads();
        if (c + 1 < 16) {
            const int k0 = (c + 1) * 32;
            const uint32_t sA = sb + (buf ^ 1)*BUF_BYTES;
            const uint32_t sW = sA + A_BYTES;
            #pragma unroll
            for (int j = 0; j < 4; j++)
                cp16(sA + (ra[j]*LDK + ca[j])*4, A + (size_t)(t0 + ra[j])*512 + k0 + ca[j]);
            #pragma unroll
            for (int j = 0; j < 8; j++)
                cp16(sW + (rw[j]*LDK + cw[j])*4, W + (size_t)(o0 + rw[j])*512 + k0 + cw[j]);
            asm volatile("cp.async.commit_group;" ::: "memory");
        }
        const uint32_t aoff = baseA + buf*BUF_BYTES;
        const uint32_t boff = baseB + buf*BUF_BYTES;
        #pragma unroll
        for (int ks = 0; ks < 4; ks++) {
            uint32_t a[4][4], b[8][2];
            #pragma unroll
            for (int mt = 0; mt < 4; mt++) {
                const uint32_t ad = aoff + (uint32_t)((mt*16*LDK + ks*8) * 4);
                asm volatile("ldmatrix.sync.aligned.m8n8.x4.shared.b16 {%0,%1,%2,%3}, [%4];"
                    : "=r"(a[mt][0]), "=r"(a[mt][1]), "=r"(a[mt][2]), "=r"(a[mt][3]) : "r"(ad));
            }
            #pragma unroll
            for (int nt = 0; nt < 8; nt++) {
                const uint32_t bd = boff + (uint32_t)((nt*8*LDK + ks*8) * 4);
                asm volatile("ldmatrix.sync.aligned.m8n8.x2.shared.b16 {%0,%1}, [%2];"
                    : "=r"(b[nt][0]), "=r"(b[nt][1]) : "r"(bd));
            }
            #pragma unroll
            for (int mt = 0; mt < 4; mt++)
                #pragma unroll
                for (int nt = 0; nt < 8; nt++) {
                    asm volatile(
                        "mma.sync.aligned.m16n8k8.row.col.f32.tf32.tf32.f32 "
                        "{%0,%1,%2,%3}, {%4,%5,%6,%7}, {%8,%9}, {%0,%1,%2,%3};"
                        : "+f"(acc[mt][nt][0]), "+f"(acc[mt][nt][1]),
                          "+f"(acc[mt][nt][2]), "+f"(acc[mt][nt][3])
                        : "r"(a[mt][0]), "r"(a[mt][1]), "r"(a[mt][2]), "r"(a[mt][3]),
                          "r"(b[nt][0]), "r"(b[nt][1]));
                }
        }
    }

    // ---- epilogue (direct global stores) ----
    const int m0g = t0 + wm*64;
    const int o0g = o0 + wn*64;
    if (EPI == 0) {
        const int i_ = o0g >> 9;
        const int h  = (o0g >> 6) & 7;
        const int b  = m0g >> 12;                 // whole block same batch
        const int rowbase = ((i_*8 + b)*8 + h) * 64;
        #pragma unroll
        for (int mt = 0; mt < 4; mt++) {
            const int t1 = m0g + mt*16 + g;
            const int n1 = t1 & 4095;
            #pragma unroll
            for (int nt = 0; nt < 8; nt++) {
                const int row = rowbase + nt*8 + tg*2;
                g_qkv[(size_t)row*4096 + n1]            = acc[mt][nt][0];
                g_qkv[(size_t)(row + 1)*4096 + n1]      = acc[mt][nt][1];
                g_qkv[(size_t)row*4096 + n1 + 8]        = acc[mt][nt][2];
                g_qkv[(size_t)(row + 1)*4096 + n1 + 8]  = acc[mt][nt][3];
            }
        }
    } else {
        #pragma unroll
        for (int mt = 0; mt < 4; mt++) {
            const int t1 = m0g + mt*16 + g;
            #pragma unroll
            for (int nt = 0; nt < 8; nt++) {
                const int o = o0g + nt*8 + tg*2;
                const float b0 = bias[o], b1 = bias[o + 1];
                float2 v0; v0.x = acc[mt][nt][0] + b0; v0.y = acc[mt][nt][1] + b1;
                float2 v1; v1.x = acc[mt][nt][2] + b0; v1.y = acc[mt][nt][3] + b1;
                *(float2*)(out + (size_t)t1*512 + o)       = v0;
                *(float2*)(out + (size_t)(t1 + 8)*512 + o) = v1;
            }
        }
    }
}

// ===========================================================================
// K3: L2-normalize q,k rows; fold temperature into q.
// ===========================================================================
__global__ void l2norm_kernel(const float* __restrict__ temperature) {
    const int row = blockIdx.x;                 // 0..8191
    float* p = g_qkv + (size_t)row * 4096;
    const int tid = threadIdx.x;                // 256
    float4 v[4];
    float ss = 0.0f;
    #pragma unroll
    for (int j = 0; j < 4; j++) {
        v[j] = *(const float4*)(p + j*1024 + tid*4);
        ss += v[j].x*v[j].x + v[j].y*v[j].y + v[j].z*v[j].z + v[j].w*v[j].w;
    }
    #pragma unroll
    for (int o = 16; o > 0; o >>= 1) ss += __shfl_xor_sync(0xffffffffu, ss, o);
    __shared__ float sh[8];
    const int w = tid >> 5, l = tid & 31;
    if (l == 0) sh[w] = ss;
    __syncthreads();
    float tot = 0.0f;
    #pragma unroll
    for (int j = 0; j < 8; j++) tot += sh[j];
    const float factor = (row < Bb*Hh*DHd) ? temperature[(row >> 6) & 7] : 1.0f;
    const float scale = factor / fmaxf(sqrtf(tot), 1e-12f);
    #pragma unroll
    for (int j = 0; j < 4; j++) {
        v[j].x *= scale; v[j].y *= scale; v[j].z *= scale; v[j].w *= scale;
        *(float4*)(p + j*1024 + tid*4) = v[j];
    }
}

// ===========================================================================
// K4a: partial S = q k^T over a 512-token slice of n. grid (64 bh, 8 splits).
// ===========================================================================
#define PAD 65
__global__ void __launch_bounds__(256) attn_qk_kernel() {
    __shared__ float qs[64*PAD];
    __shared__ float ks[64*PAD];
    const int bh = blockIdx.x;
    const int split = blockIdx.y;
    const float* __restrict__ q = g_qkv + (size_t)(0*64 + bh) * 64 * 4096;
    const float* __restrict__ k = g_qkv + (size_t)(1*64 + bh) * 64 * 4096;
    const int tid = threadIdx.x;
    const int tx = tid & 15, ty = tid >> 4;

    float S[4][4];
    #pragma unroll
    for (int i = 0; i < 4; i++)
        #pragma unroll
        for (int j = 0; j < 4; j++) S[i][j] = 0.0f;

    const int nbeg = split * 512;
    for (int n0 = nbeg; n0 < nbeg + 512; n0 += 64) {
        #pragma unroll
        for (int j = 0; j < 4; j++) {
            const int idx = j*256 + tid;
            const int r = idx >> 4;
            const int c = (idx & 15) * 4;
            float4 qv = *(const float4*)(q + (size_t)r*4096 + n0 + c);
            qs[r*PAD + c+0] = qv.x; qs[r*PAD + c+1] = qv.y;
            qs[r*PAD + c+2] = qv.z; qs[r*PAD + c+3] = qv.w;
            float4 kv = *(const float4*)(k + (size_t)r*4096 + n0 + c);
            ks[r*PAD + c+0] = kv.x; ks[r*PAD + c+1] = kv.y;
            ks[r*PAD + c+2] = kv.z; ks[r*PAD + c+3] = kv.w;
        }
        __syncthreads();
        #pragma unroll 8
        for (int n = 0; n < 64; n++) {
            float qr[4], kr[4];
            #pragma unroll
            for (int i = 0; i < 4; i++) qr[i] = qs[(ty*4+i)*PAD + n];
            #pragma unroll
            for (int j = 0; j < 4; j++) kr[j] = ks[(tx*4+j)*PAD + n];
            #pragma unroll
            for (int i = 0; i < 4; i++)
                #pragma unroll
                for (int j = 0; j < 4; j++)
                    S[i][j] = fmaf(qr[i], kr[j], S[i][j]);
        }
        __syncthreads();
    }
    float* dst = g_Sp + ((size_t)(bh*8 + split)) * 4096;
    #pragma unroll
    for (int i = 0; i < 4; i++) {
        float4 v;
        v.x = S[i][0]; v.y = S[i][1]; v.z = S[i][2]; v.w = S[i][3];
        *(float4*)(dst + (ty*4+i)*64 + tx*4) = v;
    }
}

// ===========================================================================
// K4b: reduce 8 partials + softmax over e. grid 64, block 256.
// ===========================================================================
__global__ void __launch_bounds__(256) softmax_kernel() {
    __shared__ float S[64*PAD];
    const int bh = blockIdx.x;
    const int tid = threadIdx.x;
    for (int idx = tid; idx < 4096; idx += 256) {
        float s = 0.0f;
        #pragma unroll
        for (int sp = 0; sp < 8; sp++)
            s += g_Sp[((size_t)(bh*8 + sp))*4096 + idx];
        S[(idx >> 6)*PAD + (idx & 63)] = s;
    }
    __syncthreads();
    if (tid < 64) {
        const int d = tid;
        float mx = -1e30f;
        #pragma unroll 8
        for (int e = 0; e < 64; e++) mx = fmaxf(mx, S[d*PAD + e]);
        float sm = 0.0f;
        #pragma unroll 8
        for (int e = 0; e < 64; e++) {
            const float ex = __expf(S[d*PAD + e] - mx);
            S[d*PAD + e] = ex;
            sm += ex;
        }
        const float inv = 1.0f / sm;
        #pragma unroll 8
        for (int e = 0; e < 64; e++)
            g_attn[(size_t)bh*4096 + d*64 + e] = S[d*PAD + e] * inv;
    }
}

// ===========================================================================
// K4c: out[d][n] = sum_e attn[d][e] v[e][n]; gelu; write g_y [b,n,c] (tf32-rounded).
// ===========================================================================
__global__ void __launch_bounds__(256) attn_v_kernel() {
    __shared__ float attn[64*PAD];
    __shared__ float vs[64*PAD];
    const int bh = blockIdx.x;
    const int b = bh >> 3, h = bh & 7;
    const int n0 = blockIdx.y * 64;
    const float* __restrict__ v = g_qkv + (size_t)(2*64 + bh) * 64 * 4096;
    const int tid = threadIdx.x;
    const int tx = tid & 15, ty = tid >> 4;

    for (int idx = tid; idx < 4096; idx += 256)
        attn[(idx >> 6)*PAD + (idx & 63)] = g_attn[(size_t)bh*4096 + idx];
    #pragma unroll
    for (int j = 0; j < 4; j++) {
        const int idx = j*256 + tid;
        const int r = idx >> 4;
        const int c = (idx & 15) * 4;
        float4 vv = *(const float4*)(v + (size_t)r*4096 + n0 + c);
        vs[r*PAD + c+0] = vv.x; vs[r*PAD + c+1] = vv.y;
        vs[r*PAD + c+2] = vv.z; vs[r*PAD + c+3] = vv.w;
    }
    __syncthreads();

    float acc[4][4];
    #pragma unroll
    for (int i = 0; i < 4; i++)
        #pragma unroll
        for (int j = 0; j < 4; j++) acc[i][j] = 0.0f;
    #pragma unroll 8
    for (int e = 0; e < 64; e++) {
        float ar[4], vr[4];
        #pragma unroll
        for (int j = 0; j < 4; j++) ar[j] = attn[(tx*4+j)*PAD + e];
        #pragma unroll
        for (int i = 0; i < 4; i++) vr[i] = vs[e*PAD + ty*4 + i];
        #pragma unroll
        for (int i = 0; i < 4; i++)
            #pragma unroll
            for (int j = 0; j < 4; j++)
                acc[i][j] = fmaf(ar[j], vr[i], acc[i][j]);
    }
    #pragma unroll
    for (int i = 0; i < 4; i++) {
        const int n = n0 + ty*4 + i;
        const size_t t = (size_t)b*4096 + n;
        float4 o;
        float xg;
        xg = acc[i][0]; o.x = tf32r(0.5f*xg*(1.0f + erff(xg*0.70710678118654752f)));
        xg = acc[i][1]; o.y = tf32r(0.5f*xg*(1.0f + erff(xg*0.70710678118654752f)));
        xg = acc[i][2]; o.z = tf32r(0.5f*xg*(1.0f + erff(xg*0.70710678118654752f)));
        xg = acc[i][3]; o.w = tf32r(0.5f*xg*(1.0f + erff(xg*0.70710678118654752f)));
        *(float4*)(g_y + t*512 + h*64 + tx*4) = o;
    }
}

// ===========================================================================
extern "C" void kernel_launch(void* const* d_in, const int* in_sizes, int n_in,
                              void* d_out, int out_size) {
    const float* x           = (const float*)d_in[0];
    const float* ln_g        = (const float*)d_in[1];
    const float* ln_b        = (const float*)d_in[2];
    const float* qkv_w       = (const float*)d_in[3];
    const float* temperature = (const float*)d_in[4];
    const float* proj_w      = (const float*)d_in[5];
    const float* proj_b      = (const float*)d_in[6];
    float* out = (float*)d_out;

    cudaFuncSetAttribute(mmagemm<0>, cudaFuncAttributeMaxDynamicSharedMemorySize, GEMM_SMEM);
    cudaFuncSetAttribute(mmagemm<1>, cudaFuncAttributeMaxDynamicSharedMemorySize, GEMM_SMEM);

    round_w_kernel<<<512, 256>>>(qkv_w, proj_w);
    ln_kernel<<<Tt, 128>>>(x, ln_g, ln_b);
    mmagemm<0><<<dim3(1536/256, Tt/128), 256, GEMM_SMEM>>>(nullptr, nullptr);
    l2norm_kernel<<<2*Bb*Hh*DHd, 256>>>(temperature);
    attn_qk_kernel<<<dim3(64, 8), 256>>>();
    softmax_kernel<<<64, 256>>>();
    attn_v_kernel<<<dim3(64, 64), 256>>>();
    mmagemm<1><<<dim3(512/256, Tt/128), 256, GEMM_SMEM>>>(proj_b, out);
}